// round 2
// baseline (speedup 1.0000x reference)
#include <cuda_runtime.h>
#include <cuda_bf16.h>
#include <math.h>

// total = sum_i [ 0.5*w^2 - 0.5*((w-mu)/sig)^2 - log(sig) ]   (weights)
//       + sum_j [ 0.5*((y-mup)/sp)^2 ]                         (likelihood, negated)
//       + B * (log(sp) + HALF_LOG_2PI)                         (closed-form constant)
// (HALF_LOG_2PI cancels between variational and prior terms; PRIOR_SIGMA=1.)

#define HALF_LOG_2PI 0.9189385332046727

static constexpr int BLOCKS  = 2048;
static constexpr int THREADS = 256;

__device__ double       g_partials[BLOCKS];
__device__ unsigned int g_count = 0;   // reset to 0 by the last block each launch

__device__ __forceinline__ float term5(float w, float mu, float sg,
                                       float mp, float yt, float inv_sp) {
    float z = (w - mu) * __frcp_rn(sg);
    float u = (yt - mp) * inv_sp;
    return 0.5f * w * w - 0.5f * z * z - __logf(sg) + 0.5f * u * u;
}

__global__ __launch_bounds__(THREADS, 8)
void fused_loss_kernel(const float4* __restrict__ w,
                       const float4* __restrict__ mu,
                       const float4* __restrict__ sg,
                       const float4* __restrict__ mp,
                       const float4* __restrict__ yt,
                       const float*  __restrict__ sp_ptr,
                       float* __restrict__ out,
                       int n4, int n_batch) {
    const float inv_sp = __frcp_rn(*sp_ptr);

    float acc = 0.0f;
    int stride = gridDim.x * blockDim.x;
    for (int i = blockIdx.x * blockDim.x + threadIdx.x; i < n4; i += stride) {
        float4 a = __ldg(&w[i]);
        float4 b = __ldg(&mu[i]);
        float4 c = __ldg(&sg[i]);
        float4 d = __ldg(&mp[i]);
        float4 e = __ldg(&yt[i]);
        acc += term5(a.x, b.x, c.x, d.x, e.x, inv_sp);
        acc += term5(a.y, b.y, c.y, d.y, e.y, inv_sp);
        acc += term5(a.z, b.z, c.z, d.z, e.z, inv_sp);
        acc += term5(a.w, b.w, c.w, d.w, e.w, inv_sp);
    }

    // warp reduce (float is fine for <=64 terms per thread)
    #pragma unroll
    for (int off = 16; off > 0; off >>= 1)
        acc += __shfl_xor_sync(0xFFFFFFFFu, acc, off);

    __shared__ double s_warp[THREADS / 32];
    int lane = threadIdx.x & 31;
    int wid  = threadIdx.x >> 5;
    if (lane == 0) s_warp[wid] = (double)acc;
    __syncthreads();

    __shared__ bool s_is_last;
    if (threadIdx.x == 0) {
        double bsum = 0.0;
        #pragma unroll
        for (int k = 0; k < THREADS / 32; k++) bsum += s_warp[k];
        g_partials[blockIdx.x] = bsum;
        __threadfence();
        unsigned int ticket = atomicAdd(&g_count, 1u);
        s_is_last = (ticket == (unsigned int)(gridDim.x - 1));
    }
    __syncthreads();

    if (!s_is_last) return;

    // ---- last block: deterministic final reduction over g_partials ----
    __shared__ double s_final[THREADS];
    double facc = 0.0;
    for (int i = threadIdx.x; i < BLOCKS; i += THREADS)
        facc += g_partials[i];                   // index-ordered -> deterministic
    s_final[threadIdx.x] = facc;
    __syncthreads();
    #pragma unroll
    for (int ofs = THREADS / 2; ofs > 0; ofs >>= 1) {
        if (threadIdx.x < ofs) s_final[threadIdx.x] += s_final[threadIdx.x + ofs];
        __syncthreads();
    }
    if (threadIdx.x == 0) {
        double sp = (double)(*sp_ptr);
        double c  = (double)n_batch * (log(sp) + HALF_LOG_2PI);
        out[0] = (float)(s_final[0] + c);
        g_count = 0;   // reset for next graph replay
    }
}

extern "C" void kernel_launch(void* const* d_in, const int* in_sizes, int n_in,
                              void* d_out, int out_size) {
    // metadata order: noisy_weights, mu_weights, sigma_weights,
    //                 mu_prediction, sigma_prediction (scalar), y_true
    const float4* w  = (const float4*)d_in[0];
    const float4* mu = (const float4*)d_in[1];
    const float4* sg = (const float4*)d_in[2];
    const float4* mp = (const float4*)d_in[3];
    const float*  sp = (const float*) d_in[4];
    const float4* yt = (const float4*)d_in[5];

    int n  = in_sizes[0];      // 2^24, divisible by 4
    int n4 = n >> 2;

    fused_loss_kernel<<<BLOCKS, THREADS>>>(w, mu, sg, mp, yt, sp,
                                           (float*)d_out, n4, in_sizes[5]);
}

// round 3
// speedup vs baseline: 1.1048x; 1.1048x over previous
#include <cuda_runtime.h>
#include <cuda_bf16.h>
#include <math.h>

// total = sum_i [ 0.5*w^2 - 0.5*((w-mu)/sig)^2 - log(sig) ]   (weights)
//       + sum_j [ 0.5*((y-mup)/sp)^2 ]                         (likelihood, negated)
//       + B * (log(sp) + HALF_LOG_2PI)                         (closed-form constant)

#define HALF_LOG_2PI 0.9189385332046727

static constexpr int BLOCKS  = 592;   // 148 SMs x 4 resident blocks -> single wave
static constexpr int THREADS = 256;

__device__ double       g_partials[BLOCKS];
__device__ unsigned int g_count = 0;   // reset by the last block each launch

__device__ __forceinline__ float term5(float w, float mu, float sg,
                                       float mp, float yt, float inv_sp) {
    float z = (w - mu) * __frcp_rn(sg);
    float u = (yt - mp) * inv_sp;
    return 0.5f * w * w - 0.5f * z * z - __logf(sg) + 0.5f * u * u;
}

__device__ __forceinline__ float quad(const float4& a, const float4& b,
                                      const float4& c, const float4& d,
                                      const float4& e, float inv_sp) {
    return term5(a.x, b.x, c.x, d.x, e.x, inv_sp)
         + term5(a.y, b.y, c.y, d.y, e.y, inv_sp)
         + term5(a.z, b.z, c.z, d.z, e.z, inv_sp)
         + term5(a.w, b.w, c.w, d.w, e.w, inv_sp);
}

__global__ __launch_bounds__(THREADS, 4)
void fused_loss_kernel(const float4* __restrict__ w,
                       const float4* __restrict__ mu,
                       const float4* __restrict__ sg,
                       const float4* __restrict__ mp,
                       const float4* __restrict__ yt,
                       const float*  __restrict__ sp_ptr,
                       float* __restrict__ out,
                       int n4, int n_batch) {
    const float inv_sp = __frcp_rn(*sp_ptr);
    const int stride  = gridDim.x * blockDim.x;
    const int stride2 = stride * 2;

    float acc = 0.0f;
    int i = blockIdx.x * blockDim.x + threadIdx.x;

    // main loop: 2x unrolled, all 10 LDG.128 front-batched for MLP
    for (; i + stride < n4; i += stride2) {
        int j = i + stride;
        float4 a0 = __ldcs(&w[i]);
        float4 b0 = __ldcs(&mu[i]);
        float4 c0 = __ldcs(&sg[i]);
        float4 d0 = __ldcs(&mp[i]);
        float4 e0 = __ldcs(&yt[i]);
        float4 a1 = __ldcs(&w[j]);
        float4 b1 = __ldcs(&mu[j]);
        float4 c1 = __ldcs(&sg[j]);
        float4 d1 = __ldcs(&mp[j]);
        float4 e1 = __ldcs(&yt[j]);
        acc += quad(a0, b0, c0, d0, e0, inv_sp);
        acc += quad(a1, b1, c1, d1, e1, inv_sp);
    }
    // remainder (at most one stride's worth)
    for (; i < n4; i += stride) {
        float4 a = __ldcs(&w[i]);
        float4 b = __ldcs(&mu[i]);
        float4 c = __ldcs(&sg[i]);
        float4 d = __ldcs(&mp[i]);
        float4 e = __ldcs(&yt[i]);
        acc += quad(a, b, c, d, e, inv_sp);
    }

    // warp reduce
    #pragma unroll
    for (int off = 16; off > 0; off >>= 1)
        acc += __shfl_xor_sync(0xFFFFFFFFu, acc, off);

    __shared__ double s_warp[THREADS / 32];
    int lane = threadIdx.x & 31;
    int wid  = threadIdx.x >> 5;
    if (lane == 0) s_warp[wid] = (double)acc;
    __syncthreads();

    __shared__ bool s_is_last;
    if (threadIdx.x == 0) {
        double bsum = 0.0;
        #pragma unroll
        for (int k = 0; k < THREADS / 32; k++) bsum += s_warp[k];
        g_partials[blockIdx.x] = bsum;
        __threadfence();
        unsigned int ticket = atomicAdd(&g_count, 1u);
        s_is_last = (ticket == (unsigned int)(gridDim.x - 1));
    }
    __syncthreads();

    if (!s_is_last) return;

    // ---- last block: deterministic final reduction over g_partials ----
    __shared__ double s_final[THREADS];
    double facc = 0.0;
    for (int k = threadIdx.x; k < BLOCKS; k += THREADS)
        facc += g_partials[k];                   // index-ordered -> deterministic
    s_final[threadIdx.x] = facc;
    __syncthreads();
    #pragma unroll
    for (int ofs = THREADS / 2; ofs > 0; ofs >>= 1) {
        if (threadIdx.x < ofs) s_final[threadIdx.x] += s_final[threadIdx.x + ofs];
        __syncthreads();
    }
    if (threadIdx.x == 0) {
        double sp = (double)(*sp_ptr);
        double c  = (double)n_batch * (log(sp) + HALF_LOG_2PI);
        out[0] = (float)(s_final[0] + c);
        g_count = 0;   // reset for next graph replay
    }
}

extern "C" void kernel_launch(void* const* d_in, const int* in_sizes, int n_in,
                              void* d_out, int out_size) {
    // metadata order: noisy_weights, mu_weights, sigma_weights,
    //                 mu_prediction, sigma_prediction (scalar), y_true
    const float4* w  = (const float4*)d_in[0];
    const float4* mu = (const float4*)d_in[1];
    const float4* sg = (const float4*)d_in[2];
    const float4* mp = (const float4*)d_in[3];
    const float*  sp = (const float*) d_in[4];
    const float4* yt = (const float4*)d_in[5];

    int n  = in_sizes[0];      // 2^24, divisible by 4
    int n4 = n >> 2;

    fused_loss_kernel<<<BLOCKS, THREADS>>>(w, mu, sg, mp, yt, sp,
                                           (float*)d_out, n4, in_sizes[5]);
}

// round 4
// speedup vs baseline: 1.1365x; 1.0287x over previous
#include <cuda_runtime.h>
#include <cuda_bf16.h>
#include <math.h>

// total = sum_i [ 0.5*w^2 - 0.5*((w-mu)/sig)^2 - log(sig) ]   (weights)
//       + sum_j [ 0.5*((y-mup)/sp)^2 ]                         (likelihood, negated)
//       + B * (log(sp) + HALF_LOG_2PI)                         (closed-form constant)

#define HALF_LOG_2PI 0.9189385332046727

static constexpr int BLOCKS  = 296;   // 148 SMs x 2 resident blocks -> single wave
static constexpr int THREADS = 256;

__device__ double       g_partials[BLOCKS];
__device__ unsigned int g_count = 0;   // reset by the last block each launch

__device__ __forceinline__ float frcp_fast(float x) {
    float r;
    asm("rcp.approx.ftz.f32 %0, %1;" : "=f"(r) : "f"(x));
    return r;
}

__device__ __forceinline__ float term5(float w, float mu, float sg,
                                       float mp, float yt, float inv_sp) {
    float z = (w - mu) * frcp_fast(sg);
    float u = (yt - mp) * inv_sp;
    return 0.5f * w * w - 0.5f * z * z - __logf(sg) + 0.5f * u * u;
}

__device__ __forceinline__ float quad(const float4& a, const float4& b,
                                      const float4& c, const float4& d,
                                      const float4& e, float inv_sp) {
    return term5(a.x, b.x, c.x, d.x, e.x, inv_sp)
         + term5(a.y, b.y, c.y, d.y, e.y, inv_sp)
         + term5(a.z, b.z, c.z, d.z, e.z, inv_sp)
         + term5(a.w, b.w, c.w, d.w, e.w, inv_sp);
}

__global__ __launch_bounds__(THREADS, 2)
void fused_loss_kernel(const float4* __restrict__ w,
                       const float4* __restrict__ mu,
                       const float4* __restrict__ sg,
                       const float4* __restrict__ mp,
                       const float4* __restrict__ yt,
                       const float*  __restrict__ sp_ptr,
                       float* __restrict__ out,
                       int n4, int n_batch) {
    const float inv_sp = frcp_fast(*sp_ptr);
    const int stride  = gridDim.x * blockDim.x;
    const int stride4 = stride * 4;

    float acc0 = 0.0f, acc1 = 0.0f, acc2 = 0.0f, acc3 = 0.0f;
    int i = blockIdx.x * blockDim.x + threadIdx.x;

    // main loop: 4x unrolled, all 20 LDG.128 front-batched for deep MLP
    for (; i + 3 * stride < n4; i += stride4) {
        int i1 = i + stride, i2 = i + 2 * stride, i3 = i + 3 * stride;
        float4 a0 = __ldcs(&w[i]),  b0 = __ldcs(&mu[i]),  c0 = __ldcs(&sg[i]),
               d0 = __ldcs(&mp[i]), e0 = __ldcs(&yt[i]);
        float4 a1 = __ldcs(&w[i1]), b1 = __ldcs(&mu[i1]), c1 = __ldcs(&sg[i1]),
               d1 = __ldcs(&mp[i1]), e1 = __ldcs(&yt[i1]);
        float4 a2 = __ldcs(&w[i2]), b2 = __ldcs(&mu[i2]), c2 = __ldcs(&sg[i2]),
               d2 = __ldcs(&mp[i2]), e2 = __ldcs(&yt[i2]);
        float4 a3 = __ldcs(&w[i3]), b3 = __ldcs(&mu[i3]), c3 = __ldcs(&sg[i3]),
               d3 = __ldcs(&mp[i3]), e3 = __ldcs(&yt[i3]);
        acc0 += quad(a0, b0, c0, d0, e0, inv_sp);
        acc1 += quad(a1, b1, c1, d1, e1, inv_sp);
        acc2 += quad(a2, b2, c2, d2, e2, inv_sp);
        acc3 += quad(a3, b3, c3, d3, e3, inv_sp);
    }
    // remainder (< 3 strides' worth)
    for (; i < n4; i += stride) {
        float4 a = __ldcs(&w[i]), b = __ldcs(&mu[i]), c = __ldcs(&sg[i]),
               d = __ldcs(&mp[i]), e = __ldcs(&yt[i]);
        acc0 += quad(a, b, c, d, e, inv_sp);
    }

    float acc = (acc0 + acc1) + (acc2 + acc3);

    // warp reduce
    #pragma unroll
    for (int off = 16; off > 0; off >>= 1)
        acc += __shfl_xor_sync(0xFFFFFFFFu, acc, off);

    __shared__ double s_warp[THREADS / 32];
    int lane = threadIdx.x & 31;
    int wid  = threadIdx.x >> 5;
    if (lane == 0) s_warp[wid] = (double)acc;
    __syncthreads();

    __shared__ bool s_is_last;
    if (threadIdx.x == 0) {
        double bsum = 0.0;
        #pragma unroll
        for (int k = 0; k < THREADS / 32; k++) bsum += s_warp[k];
        g_partials[blockIdx.x] = bsum;
        __threadfence();
        unsigned int ticket = atomicAdd(&g_count, 1u);
        s_is_last = (ticket == (unsigned int)(gridDim.x - 1));
    }
    __syncthreads();

    if (!s_is_last) return;

    // ---- last block: deterministic final reduction over g_partials ----
    __shared__ double s_final[THREADS];
    double facc = 0.0;
    for (int k = threadIdx.x; k < BLOCKS; k += THREADS)
        facc += g_partials[k];                   // index-ordered -> deterministic
    s_final[threadIdx.x] = facc;
    __syncthreads();
    #pragma unroll
    for (int ofs = THREADS / 2; ofs > 0; ofs >>= 1) {
        if (threadIdx.x < ofs) s_final[threadIdx.x] += s_final[threadIdx.x + ofs];
        __syncthreads();
    }
    if (threadIdx.x == 0) {
        double sp = (double)(*sp_ptr);
        double c  = (double)n_batch * (log(sp) + HALF_LOG_2PI);
        out[0] = (float)(s_final[0] + c);
        g_count = 0;   // reset for next graph replay
    }
}

extern "C" void kernel_launch(void* const* d_in, const int* in_sizes, int n_in,
                              void* d_out, int out_size) {
    // metadata order: noisy_weights, mu_weights, sigma_weights,
    //                 mu_prediction, sigma_prediction (scalar), y_true
    const float4* w  = (const float4*)d_in[0];
    const float4* mu = (const float4*)d_in[1];
    const float4* sg = (const float4*)d_in[2];
    const float4* mp = (const float4*)d_in[3];
    const float*  sp = (const float*) d_in[4];
    const float4* yt = (const float4*)d_in[5];

    int n  = in_sizes[0];      // 2^24, divisible by 4
    int n4 = n >> 2;

    fused_loss_kernel<<<BLOCKS, THREADS>>>(w, mu, sg, mp, yt, sp,
                                           (float*)d_out, n4, in_sizes[5]);
}

// round 5
// speedup vs baseline: 1.1457x; 1.0081x over previous
#include <cuda_runtime.h>
#include <cuda_bf16.h>
#include <math.h>

// total = sum_i [ 0.5*w^2 - 0.5*((w-mu)/sig)^2 - log(sig) ]   (weights)
//       + sum_j [ 0.5*((y-mup)/sp)^2 ]                         (likelihood, negated)
//       + B * (log(sp) + HALF_LOG_2PI)                         (closed-form constant)

#define HALF_LOG_2PI 0.9189385332046727

static constexpr int    BLOCKS  = 296;   // 148 SMs x 2 resident blocks -> single wave
static constexpr int    THREADS = 256;
static constexpr double FXSCALE = 4194304.0;   // 2^22 fixed-point scale

__device__ long long    g_sum   = 0;   // fixed-point accumulator (order-independent)
__device__ unsigned int g_count = 0;   // arrival ticket; reset each launch

__device__ __forceinline__ float frcp_fast(float x) {
    float r;
    asm("rcp.approx.ftz.f32 %0, %1;" : "=f"(r) : "f"(x));
    return r;
}

// streaming LDG.128 with L2 256B prefetch hint
__device__ __forceinline__ float4 ldcs_pf(const float4* p) {
    float4 v;
    asm volatile("ld.global.cs.L2::256B.v4.f32 {%0,%1,%2,%3}, [%4];"
                 : "=f"(v.x), "=f"(v.y), "=f"(v.z), "=f"(v.w) : "l"(p));
    return v;
}

__device__ __forceinline__ float term5(float w, float mu, float sg,
                                       float mp, float yt, float inv_sp) {
    float z = (w - mu) * frcp_fast(sg);
    float u = (yt - mp) * inv_sp;
    return 0.5f * w * w - 0.5f * z * z - __logf(sg) + 0.5f * u * u;
}

__device__ __forceinline__ float quad(const float4& a, const float4& b,
                                      const float4& c, const float4& d,
                                      const float4& e, float inv_sp) {
    return term5(a.x, b.x, c.x, d.x, e.x, inv_sp)
         + term5(a.y, b.y, c.y, d.y, e.y, inv_sp)
         + term5(a.z, b.z, c.z, d.z, e.z, inv_sp)
         + term5(a.w, b.w, c.w, d.w, e.w, inv_sp);
}

__global__ __launch_bounds__(THREADS, 2)
void fused_loss_kernel(const float4* __restrict__ w,
                       const float4* __restrict__ mu,
                       const float4* __restrict__ sg,
                       const float4* __restrict__ mp,
                       const float4* __restrict__ yt,
                       const float*  __restrict__ sp_ptr,
                       float* __restrict__ out,
                       int n4, int n_batch) {
    const float inv_sp = frcp_fast(*sp_ptr);
    const int stride  = gridDim.x * blockDim.x;
    const int stride4 = stride * 4;

    float acc0 = 0.0f, acc1 = 0.0f, acc2 = 0.0f, acc3 = 0.0f;
    int i = blockIdx.x * blockDim.x + threadIdx.x;

    // main loop: 4x unrolled, all 20 LDG.128 front-batched
    for (; i + 3 * stride < n4; i += stride4) {
        int i1 = i + stride, i2 = i + 2 * stride, i3 = i + 3 * stride;
        float4 a0 = ldcs_pf(&w[i]),  b0 = ldcs_pf(&mu[i]),  c0 = ldcs_pf(&sg[i]),
               d0 = ldcs_pf(&mp[i]), e0 = ldcs_pf(&yt[i]);
        float4 a1 = ldcs_pf(&w[i1]), b1 = ldcs_pf(&mu[i1]), c1 = ldcs_pf(&sg[i1]),
               d1 = ldcs_pf(&mp[i1]), e1 = ldcs_pf(&yt[i1]);
        float4 a2 = ldcs_pf(&w[i2]), b2 = ldcs_pf(&mu[i2]), c2 = ldcs_pf(&sg[i2]),
               d2 = ldcs_pf(&mp[i2]), e2 = ldcs_pf(&yt[i2]);
        float4 a3 = ldcs_pf(&w[i3]), b3 = ldcs_pf(&mu[i3]), c3 = ldcs_pf(&sg[i3]),
               d3 = ldcs_pf(&mp[i3]), e3 = ldcs_pf(&yt[i3]);
        acc0 += quad(a0, b0, c0, d0, e0, inv_sp);
        acc1 += quad(a1, b1, c1, d1, e1, inv_sp);
        acc2 += quad(a2, b2, c2, d2, e2, inv_sp);
        acc3 += quad(a3, b3, c3, d3, e3, inv_sp);
    }
    for (; i < n4; i += stride) {
        float4 a = ldcs_pf(&w[i]), b = ldcs_pf(&mu[i]), c = ldcs_pf(&sg[i]),
               d = ldcs_pf(&mp[i]), e = ldcs_pf(&yt[i]);
        acc0 += quad(a, b, c, d, e, inv_sp);
    }

    float acc = (acc0 + acc1) + (acc2 + acc3);

    // warp reduce
    #pragma unroll
    for (int off = 16; off > 0; off >>= 1)
        acc += __shfl_xor_sync(0xFFFFFFFFu, acc, off);

    __shared__ double s_warp[THREADS / 32];
    int lane = threadIdx.x & 31;
    int wid  = threadIdx.x >> 5;
    if (lane == 0) s_warp[wid] = (double)acc;
    __syncthreads();

    if (threadIdx.x == 0) {
        double bsum = 0.0;
        #pragma unroll
        for (int k = 0; k < THREADS / 32; k++) bsum += s_warp[k];

        // fixed-point contribution: integer adds are order-independent -> deterministic
        long long fx = __double2ll_rn(bsum * FXSCALE);
        atomicAdd((unsigned long long*)&g_sum, (unsigned long long)fx);
        __threadfence();
        unsigned int ticket = atomicAdd(&g_count, 1u);
        if (ticket == (unsigned int)(gridDim.x - 1)) {
            long long total_fx =
                (long long)atomicAdd((unsigned long long*)&g_sum, 0ull);
            double total = (double)total_fx / FXSCALE;
            double sp = (double)(*sp_ptr);
            double c  = (double)n_batch * (log(sp) + HALF_LOG_2PI);
            out[0] = (float)(total + c);
            g_sum   = 0;   // reset for next graph replay
            g_count = 0;
        }
    }
}

extern "C" void kernel_launch(void* const* d_in, const int* in_sizes, int n_in,
                              void* d_out, int out_size) {
    // metadata order: noisy_weights, mu_weights, sigma_weights,
    //                 mu_prediction, sigma_prediction (scalar), y_true
    const float4* w  = (const float4*)d_in[0];
    const float4* mu = (const float4*)d_in[1];
    const float4* sg = (const float4*)d_in[2];
    const float4* mp = (const float4*)d_in[3];
    const float*  sp = (const float*) d_in[4];
    const float4* yt = (const float4*)d_in[5];

    int n  = in_sizes[0];      // 2^24, divisible by 4
    int n4 = n >> 2;

    fused_loss_kernel<<<BLOCKS, THREADS>>>(w, mu, sg, mp, yt, sp,
                                           (float*)d_out, n4, in_sizes[5]);
}